// round 2
// baseline (speedup 1.0000x reference)
#include <cuda_runtime.h>

#define Bdim 16
#define Npts 4096
#define Mq   1024
#define CIN  64
#define KNN  32
#define CH   (CIN + 3)   // 67 input channels (rel xyz + features)
#define H1   64
#define H2   128

// neighbor index scratch (order within each group irrelevant: downstream is
// gather + max-pool, permutation invariant)
__device__ int g_nn[Bdim * Mq * KNN];
__device__ int g_idx64;   // 1 if idx buffer is int64, 0 if int32

// ---------------------------------------------------------------------------
// helpers
// ---------------------------------------------------------------------------
__device__ __forceinline__ unsigned long long pack2(float lo, float hi) {
    unsigned long long r;
    asm("mov.b64 %0, {%1, %2};" : "=l"(r) : "f"(lo), "f"(hi));
    return r;
}
__device__ __forceinline__ void unpack2(unsigned long long v, float& lo, float& hi) {
    asm("mov.b64 {%0, %1}, %2;" : "=f"(lo), "=f"(hi) : "l"(v));
}
__device__ __forceinline__ unsigned long long fma2(unsigned long long a,
                                                   unsigned long long b,
                                                   unsigned long long c) {
    unsigned long long r;
    asm("fma.rn.f32x2 %0, %1, %2, %3;" : "=l"(r) : "l"(a), "l"(b), "l"(c));
    return r;
}

__device__ __forceinline__ long long load_idx(const void* idxp, int i) {
    if (g_idx64) return ((const long long*)idxp)[i];
    return (long long)((const int*)idxp)[i];
}

// ---------------------------------------------------------------------------
// idx dtype detection: if idx is int64, the high 32 bits of every entry are 0
// (values in [0, 4096)). If int32, odd int32 words are independent indices —
// probability all 64 sampled are zero is (1/4096)^64 ~ 0.
// ---------------------------------------------------------------------------
__global__ void detect_idx_kernel(const int* idx32) {
    if (threadIdx.x == 0) {
        int is64 = 1;
        for (int i = 0; i < 64; ++i)
            if (idx32[2 * i + 1] != 0) { is64 = 0; break; }
        g_idx64 = is64;
    }
}

// ---------------------------------------------------------------------------
// KNN kernel: one thread per query, max-heap of 32 (d2, idx) in local memory.
// Strict < replacement with ascending candidate index == top_k tie semantics.
// ---------------------------------------------------------------------------
#define KNN_TPB  64
#define CHUNK    2048

__device__ __forceinline__ void heap_sift(float* hd, int* hi, int r) {
    float dv = hd[r];
    int   iv = hi[r];
    int i = r;
    while (true) {
        int c = 2 * i + 1;
        if (c >= KNN) break;
        int c2 = c + 1;
        float cd = hd[c];
        if (c2 < KNN && hd[c2] > cd) { c = c2; cd = hd[c2]; }
        if (cd > dv) { hd[i] = cd; hi[i] = hi[c]; i = c; }
        else break;
    }
    hd[i] = dv;
    hi[i] = iv;
}

__global__ void __launch_bounds__(KNN_TPB)
knn_kernel(const float* __restrict__ pos,
           const void*  __restrict__ idxp,
           float* __restrict__ out_posq)
{
    __shared__ float4 sp[CHUNK];   // (x, y, z, |p|^2)  -> 32 KB

    const int blocks_per_batch = Mq / KNN_TPB;             // 16
    const int b = blockIdx.x / blocks_per_batch;
    const int m = (blockIdx.x % blocks_per_batch) * KNN_TPB + threadIdx.x;

    const float* posb = pos + (size_t)b * Npts * 3;

    long long qi = load_idx(idxp, b * Mq + m);
    float qx = posb[qi * 3 + 0];
    float qy = posb[qi * 3 + 1];
    float qz = posb[qi * 3 + 2];
    float qn = qx * qx + qy * qy + qz * qz;

    // first output component: pos_q
    float* pq = out_posq + (size_t)(b * Mq + m) * 3;
    pq[0] = qx; pq[1] = qy; pq[2] = qz;

    float hd[KNN];
    int   hi[KNN];

    for (int chunk = 0; chunk < Npts; chunk += CHUNK) {
        __syncthreads();
        for (int i = threadIdx.x; i < CHUNK; i += KNN_TPB) {
            int n = chunk + i;
            float px = posb[n * 3 + 0];
            float py = posb[n * 3 + 1];
            float pz = posb[n * 3 + 2];
            sp[i] = make_float4(px, py, pz, px * px + py * py + pz * pz);
        }
        __syncthreads();

        int i0 = 0;
        if (chunk == 0) {
            // fill heap with first 32 candidates, then heapify
            for (int i = 0; i < KNN; ++i) {
                float4 p = sp[i];
                float dot = fmaf(qx, p.x, fmaf(qy, p.y, qz * p.z));
                hd[i] = fmaf(-2.0f, dot, p.w + qn);
                hi[i] = i;
            }
            for (int r = KNN / 2 - 1; r >= 0; --r) heap_sift(hd, hi, r);
            i0 = KNN;
        }

        float root = hd[0];
#pragma unroll 4
        for (int i = i0; i < CHUNK; ++i) {
            float4 p = sp[i];
            float dot = fmaf(qx, p.x, fmaf(qy, p.y, qz * p.z));
            float d2  = fmaf(-2.0f, dot, p.w + qn);
            if (d2 < root) {
                hd[0] = d2;
                hi[0] = chunk + i;
                heap_sift(hd, hi, 0);
                root = hd[0];
            }
        }
    }

    int* dst = g_nn + (size_t)(b * Mq + m) * KNN;
#pragma unroll
    for (int i = 0; i < KNN; ++i) dst[i] = hi[i];
}

// ---------------------------------------------------------------------------
// Fused gather + 2-layer MLP + max-pool kernel. One block per query.
// 256 threads: W2 columns live in registers as packed f32x2 pairs.
// ---------------------------------------------------------------------------
#define MLP_TPB 256
#define XPITCH  68   // 67 channels + 1 pad

__global__ void __launch_bounds__(MLP_TPB, 2)
mlp_kernel(const float* __restrict__ pos,
           const float* __restrict__ feat,
           const float* __restrict__ W1,
           const float* __restrict__ b1,
           const float* __restrict__ W2,
           const float* __restrict__ b2,
           const void*  __restrict__ idxp,
           float* __restrict__ outp)
{
    __shared__ float W1s[CH * H1];       // [c][j], pitch 64  (17.2 KB)
    __shared__ float b1s[H1];
    __shared__ float xs[KNN * XPITCH];   // [k][c], pitch 68  (8.7 KB)
    __shared__ float h1s[KNN * H1];      // [k][j], pitch 64  (8 KB)
    __shared__ float red[H2];

    const int t = threadIdx.x;
    const int q = blockIdx.x;            // 0 .. 16383
    const int b = q >> 10;
    const int m = q & 1023;

    // ---- stage weights ----
    for (int i = t; i < CH * H1; i += MLP_TPB) W1s[i] = W1[i];
    if (t < H1) b1s[t] = b1[t];

    const int d = t & 127;               // output channel for phase 2
    unsigned long long w2r[H1 / 2];      // W2 column as 32 packed f32x2
#pragma unroll
    for (int j2 = 0; j2 < H1 / 2; ++j2) {
        float wlo = W2[(2 * j2)     * H2 + d];
        float whi = W2[(2 * j2 + 1) * H2 + d];
        w2r[j2] = pack2(wlo, whi);
    }
    const float b2d = b2[d];

    // ---- query position ----
    const float* posb = pos + (size_t)b * Npts * 3;
    long long qi = load_idx(idxp, b * Mq + m);
    const float qx = posb[qi * 3 + 0];
    const float qy = posb[qi * 3 + 1];
    const float qz = posb[qi * 3 + 2];

    // ---- gather: 8 threads per neighbor ----
    const int k  = t >> 3;               // 0..31
    const int tg = t & 7;                // 0..7
    const int n  = g_nn[(size_t)q * KNN + k];
    if (tg == 0) {
        xs[k * XPITCH + 0] = posb[n * 3 + 0] - qx;
        xs[k * XPITCH + 1] = posb[n * 3 + 1] - qy;
        xs[k * XPITCH + 2] = posb[n * 3 + 2] - qz;
    }
    const float4* f4 = (const float4*)(feat + ((size_t)b * Npts + n) * CIN);
#pragma unroll
    for (int r = 0; r < 2; ++r) {
        float4 v = f4[tg + 8 * r];
        int c0 = 3 + 4 * (tg + 8 * r);
        xs[k * XPITCH + c0 + 0] = v.x;
        xs[k * XPITCH + c0 + 1] = v.y;
        xs[k * XPITCH + c0 + 2] = v.z;
        xs[k * XPITCH + c0 + 3] = v.w;
    }
    __syncthreads();

    // ---- MLP1: thread (k = t>>3, jg = t&7) computes h1[k][jg*8 .. jg*8+7] ----
    {
        const int jg = tg;
        float acc[8];
#pragma unroll
        for (int i = 0; i < 8; ++i) acc[i] = b1s[jg * 8 + i];
        const float* xrow = xs + k * XPITCH;
        for (int c = 0; c < CH; ++c) {
            float x = xrow[c];
            const float4* wr = (const float4*)(W1s + c * H1 + jg * 8);
            float4 wa = wr[0];
            float4 wb = wr[1];
            acc[0] = fmaf(x, wa.x, acc[0]);
            acc[1] = fmaf(x, wa.y, acc[1]);
            acc[2] = fmaf(x, wa.z, acc[2]);
            acc[3] = fmaf(x, wa.w, acc[3]);
            acc[4] = fmaf(x, wb.x, acc[4]);
            acc[5] = fmaf(x, wb.y, acc[5]);
            acc[6] = fmaf(x, wb.z, acc[6]);
            acc[7] = fmaf(x, wb.w, acc[7]);
        }
        float* hrow = h1s + k * H1 + jg * 8;
#pragma unroll
        for (int i = 0; i < 8; ++i) hrow[i] = fmaxf(acc[i], 0.0f);
    }
    __syncthreads();

    // ---- MLP2 + relu + max-pool: thread t -> (d = t&127, half = t>>7) ----
    float best = 0.0f;                   // relu outputs are >= 0
    const int kbase = (t >> 7) * 16;
    for (int kk = 0; kk < 16; ++kk) {
        const int k2 = kbase + kk;
        const unsigned long long* hp =
            (const unsigned long long*)(h1s + k2 * H1);
        unsigned long long acc2 = 0ull;  // (0.0f, 0.0f)
#pragma unroll
        for (int j2 = 0; j2 < H1 / 2; ++j2)
            acc2 = fma2(hp[j2], w2r[j2], acc2);
        float lo, hiv;
        unpack2(acc2, lo, hiv);
        float s = lo + hiv + b2d;
        best = fmaxf(best, s);           // fmax with 0-init == relu-then-max
    }

    if (t >= 128) red[d] = best;
    __syncthreads();
    if (t < 128) {
        best = fmaxf(best, red[d]);
        outp[(size_t)q * H2 + d] = best;
    }
}

// ---------------------------------------------------------------------------
// launcher
// ---------------------------------------------------------------------------
extern "C" void kernel_launch(void* const* d_in, const int* in_sizes, int n_in,
                              void* d_out, int out_size)
{
    const float* pos  = (const float*)d_in[0];   // [16,4096,3]
    const float* feat = (const float*)d_in[1];   // [16,4096,64]
    const float* W1   = (const float*)d_in[2];   // [67,64]
    const float* b1   = (const float*)d_in[3];   // [64]
    const float* W2   = (const float*)d_in[4];   // [64,128]
    const float* b2   = (const float*)d_in[5];   // [128]
    const void*  idxp = d_in[6];                 // [16,1024] int64 or int32

    float* out_posq = (float*)d_out;                          // 16*1024*3
    float* out_feat = (float*)d_out + (size_t)Bdim * Mq * 3;  // 16*1024*128

    detect_idx_kernel<<<1, 32>>>((const int*)idxp);

    knn_kernel<<<Bdim * (Mq / KNN_TPB), KNN_TPB>>>(pos, idxp, out_posq);

    mlp_kernel<<<Bdim * Mq, MLP_TPB>>>(pos, feat, W1, b1, W2, b2, idxp, out_feat);
}

// round 3
// speedup vs baseline: 3.8576x; 3.8576x over previous
#include <cuda_runtime.h>

#define Bdim 16
#define Npts 4096
#define Mq   1024
#define CIN  64
#define KNN  32
#define CH   (CIN + 3)   // 67 input channels (rel xyz + features)
#define H1   64
#define H2   128

// neighbor index scratch (order within each group irrelevant: downstream is
// gather + max-pool, permutation invariant)
__device__ int g_nn[Bdim * Mq * KNN];

// ---------------------------------------------------------------------------
// helpers
// ---------------------------------------------------------------------------
__device__ __forceinline__ unsigned long long pack2(float lo, float hi) {
    unsigned long long r;
    asm("mov.b64 %0, {%1, %2};" : "=l"(r) : "f"(lo), "f"(hi));
    return r;
}
__device__ __forceinline__ void unpack2(unsigned long long v, float& lo, float& hi) {
    asm("mov.b64 {%0, %1}, %2;" : "=f"(lo), "=f"(hi) : "l"(v));
}
__device__ __forceinline__ unsigned long long fma2(unsigned long long a,
                                                   unsigned long long b,
                                                   unsigned long long c) {
    unsigned long long r;
    asm("fma.rn.f32x2 %0, %1, %2, %3;" : "=l"(r) : "l"(a), "l"(b), "l"(c));
    return r;
}

// idx dtype detection: int64 values < 4096 -> all odd 32-bit words are 0.
// If int32, 8 independent uniform [0,4096) entries all zero: p ~ 4096^-8.
__device__ __forceinline__ int idx_is64(const void* idxp) {
    const int* p = (const int*)idxp;
    int acc = p[1] | p[3] | p[5] | p[7] | p[9] | p[11] | p[13] | p[15];
    return acc == 0;
}
__device__ __forceinline__ long long load_idx2(const void* idxp, int i, int is64) {
    return is64 ? ((const long long*)idxp)[i] : (long long)((const int*)idxp)[i];
}

// ordered-float transform: total order on float bits as unsigned
__device__ __forceinline__ unsigned ordflt(float f) {
    unsigned fb = __float_as_uint(f);
    return fb ^ ((unsigned)((int)fb >> 31) | 0x80000000u);
}

// ---------------------------------------------------------------------------
// KNN kernel v2: warp per query, divergence-free 3-scan radix select.
//   pass 1: 64-bin histogram over key bits [31:26]
//   pass 2: 256-bin refine over bits [25:18] within boundary bin
//   pass 3: ballot-compacted collection; boundary ties resolved from a small
//           list by full (key,idx) order.
// Output SET matches nearest-32 (order within group irrelevant downstream).
// ---------------------------------------------------------------------------
#define QPB    8      // queries per block (1 per warp)
#define KTPB   256
#define KCHUNK 2048   // float4 tile: 32KB

__global__ void __launch_bounds__(KTPB)
knn_kernel(const float* __restrict__ pos,
           const void*  __restrict__ idxp,
           float* __restrict__ out_posq)
{
    __shared__ float4 sp[KCHUNK];                   // 32 KB, shared by 8 queries
    __shared__ unsigned h1s[QPB][64];               // 2 KB
    __shared__ unsigned h2s[QPB][257];              // ~8 KB (pad)
    __shared__ unsigned long long blist[QPB][128];  // 8 KB

    const int tid  = threadIdx.x;
    const int w    = tid >> 5;
    const int lane = tid & 31;
    const int b    = blockIdx.x >> 7;                 // 128 blocks per batch
    const int m    = ((blockIdx.x & 127) << 3) | w;
    const int q    = (b << 10) | m;

    const float* posb = pos + b * Npts * 3;

    const int is64 = idx_is64(idxp);
    const long long qi = load_idx2(idxp, q, is64);
    const float qx = posb[qi * 3 + 0];
    const float qy = posb[qi * 3 + 1];
    const float qz = posb[qi * 3 + 2];
    const float qn = qx * qx + qy * qy + qz * qz;

    if (lane == 0) {
        out_posq[q * 3 + 0] = qx;
        out_posq[q * 3 + 1] = qy;
        out_posq[q * 3 + 2] = qz;
    }

    // zero histograms (warp-local)
    h1s[w][lane] = 0; h1s[w][lane + 32] = 0;
    for (int i = lane; i < 256; i += 32) h2s[w][i] = 0;
    __syncwarp();

    // ---------------- pass 1: coarse histogram ----------------
    for (int c0 = 0; c0 < Npts; c0 += KCHUNK) {
        __syncthreads();
        for (int i = tid; i < KCHUNK; i += KTPB) {
            int n = c0 + i;
            float px = posb[n * 3 + 0];
            float py = posb[n * 3 + 1];
            float pz = posb[n * 3 + 2];
            sp[i] = make_float4(px, py, pz, px * px + py * py + pz * pz);
        }
        __syncthreads();
        for (int i = lane; i < KCHUNK; i += 32) {
            float4 p = sp[i];
            float d2 = fmaf(-2.0f, fmaf(qx, p.x, fmaf(qy, p.y, qz * p.z)), qn + p.w);
            unsigned bin = ordflt(d2) >> 26;
            unsigned mm = __match_any_sync(0xffffffffu, bin);
            if (lane == (__ffs(mm) - 1))
                atomicAdd(&h1s[w][bin], (unsigned)__popc(mm));
        }
    }
    __syncwarp();

    int B1 = 0, below1 = 0;
    if (lane == 0) {
        unsigned cum = 0;
        int i = 0;
        for (; i < 64; ++i) {
            unsigned c = h1s[w][i];
            if (cum + c >= (unsigned)KNN) break;
            cum += c;
        }
        B1 = i; below1 = (int)cum;
    }
    B1 = __shfl_sync(0xffffffffu, B1, 0);
    below1 = __shfl_sync(0xffffffffu, below1, 0);

    // ---------------- pass 2: refine within boundary bin ----------------
    for (int c0 = 0; c0 < Npts; c0 += KCHUNK) {
        __syncthreads();
        for (int i = tid; i < KCHUNK; i += KTPB) {
            int n = c0 + i;
            float px = posb[n * 3 + 0];
            float py = posb[n * 3 + 1];
            float pz = posb[n * 3 + 2];
            sp[i] = make_float4(px, py, pz, px * px + py * py + pz * pz);
        }
        __syncthreads();
        for (int i = lane; i < KCHUNK; i += 32) {
            float4 p = sp[i];
            float d2 = fmaf(-2.0f, fmaf(qx, p.x, fmaf(qy, p.y, qz * p.z)), qn + p.w);
            unsigned orf = ordflt(d2);
            if ((int)(orf >> 26) == B1)
                atomicAdd(&h2s[w][(orf >> 18) & 0xFF], 1u);
        }
    }
    __syncwarp();

    int B2 = 0, below2 = 0;
    if (lane == 0) {
        unsigned cum = (unsigned)below1;
        int i = 0;
        for (; i < 256; ++i) {
            unsigned c = h2s[w][i];
            if (cum + c >= (unsigned)KNN) break;
            cum += c;
        }
        B2 = i; below2 = (int)cum;
    }
    B2 = __shfl_sync(0xffffffffu, B2, 0);
    below2 = __shfl_sync(0xffffffffu, below2, 0);

    // ---------------- pass 3: collect ----------------
    int outn = 0;   // definite-select running count (== below2 at end)
    int brun = 0;   // boundary-list running count
    int* dst = g_nn + q * KNN;

    for (int c0 = 0; c0 < Npts; c0 += KCHUNK) {
        __syncthreads();
        for (int i = tid; i < KCHUNK; i += KTPB) {
            int n = c0 + i;
            float px = posb[n * 3 + 0];
            float py = posb[n * 3 + 1];
            float pz = posb[n * 3 + 2];
            sp[i] = make_float4(px, py, pz, px * px + py * py + pz * pz);
        }
        __syncthreads();
        for (int i = lane; i < KCHUNK; i += 32) {
            float4 p = sp[i];
            float d2 = fmaf(-2.0f, fmaf(qx, p.x, fmaf(qy, p.y, qz * p.z)), qn + p.w);
            unsigned orf = ordflt(d2);
            int b1v = (int)(orf >> 26);
            int sub = (int)((orf >> 18) & 0xFF);
            bool sel = (b1v < B1) || ((b1v == B1) && (sub < B2));
            bool bnd = (b1v == B1) && (sub == B2);

            unsigned sm = __ballot_sync(0xffffffffu, sel);
            if (sel)
                dst[outn + __popc(sm & ((1u << lane) - 1u))] = c0 + i;
            outn += __popc(sm);

            unsigned bm = __ballot_sync(0xffffffffu, bnd);
            if (bnd) {
                int s = brun + __popc(bm & ((1u << lane) - 1u));
                if (s < 128)
                    blist[w][s] = ((unsigned long long)orf << 32) | (unsigned)(c0 + i);
            }
            brun += __popc(bm);
        }
    }
    __syncwarp();

    // fill remaining r = 32 - below2 slots from the boundary list (tiny)
    if (lane == 0) {
        int cnt = brun < 128 ? brun : 128;
        int r = KNN - outn;
        for (int s = 0; s < r; ++s) {
            unsigned long long bk = ~0ull;
            int bj = 0;
            for (int j = 0; j < cnt; ++j) {
                unsigned long long v = blist[w][j];
                if (v < bk) { bk = v; bj = j; }
            }
            dst[outn + s] = (int)(bk & 0xffffffffu);
            blist[w][bj] = ~0ull;
        }
    }
}

// ---------------------------------------------------------------------------
// Fused gather + 2-layer MLP + max-pool kernel. One block per query.
// W2 column registers loaded AFTER phase 1 to shrink peak register pressure.
// ---------------------------------------------------------------------------
#define MLP_TPB 256
#define XPITCH  68   // 67 channels + 1 pad

__global__ void __launch_bounds__(MLP_TPB, 2)
mlp_kernel(const float* __restrict__ pos,
           const float* __restrict__ feat,
           const float* __restrict__ W1,
           const float* __restrict__ b1,
           const float* __restrict__ W2,
           const float* __restrict__ b2,
           const void*  __restrict__ idxp,
           float* __restrict__ outp)
{
    __shared__ float W1s[CH * H1];       // [c][j], pitch 64  (17.2 KB)
    __shared__ float b1s[H1];
    __shared__ float xs[KNN * XPITCH];   // [k][c], pitch 68  (8.7 KB)
    __shared__ float h1s[KNN * H1];      // [k][j], pitch 64  (8 KB)
    __shared__ float red[H2];

    const int t = threadIdx.x;
    const int q = blockIdx.x;            // 0 .. 16383
    const int b = q >> 10;
    const int m = q & 1023;

    // ---- stage weights ----
    for (int i = t; i < CH * H1; i += MLP_TPB) W1s[i] = W1[i];
    if (t < H1) b1s[t] = b1[t];

    // ---- query position ----
    const float* posb = pos + (size_t)b * Npts * 3;
    const int is64 = idx_is64(idxp);
    long long qi = load_idx2(idxp, b * Mq + m, is64);
    const float qx = posb[qi * 3 + 0];
    const float qy = posb[qi * 3 + 1];
    const float qz = posb[qi * 3 + 2];

    // ---- gather: 8 threads per neighbor ----
    const int k  = t >> 3;               // 0..31
    const int tg = t & 7;                // 0..7
    const int n  = g_nn[(size_t)q * KNN + k];
    if (tg == 0) {
        xs[k * XPITCH + 0] = posb[n * 3 + 0] - qx;
        xs[k * XPITCH + 1] = posb[n * 3 + 1] - qy;
        xs[k * XPITCH + 2] = posb[n * 3 + 2] - qz;
    }
    const float4* f4 = (const float4*)(feat + ((size_t)b * Npts + n) * CIN);
#pragma unroll
    for (int r = 0; r < 2; ++r) {
        float4 v = f4[tg + 8 * r];
        int c0 = 3 + 4 * (tg + 8 * r);
        xs[k * XPITCH + c0 + 0] = v.x;
        xs[k * XPITCH + c0 + 1] = v.y;
        xs[k * XPITCH + c0 + 2] = v.z;
        xs[k * XPITCH + c0 + 3] = v.w;
    }
    __syncthreads();

    // ---- MLP1: thread (k = t>>3, jg = t&7) computes h1[k][jg*8 .. jg*8+7] ----
    {
        const int jg = tg;
        float acc[8];
#pragma unroll
        for (int i = 0; i < 8; ++i) acc[i] = b1s[jg * 8 + i];
        const float* xrow = xs + k * XPITCH;
        for (int c = 0; c < CH; ++c) {
            float x = xrow[c];
            const float4* wr = (const float4*)(W1s + c * H1 + jg * 8);
            float4 wa = wr[0];
            float4 wb = wr[1];
            acc[0] = fmaf(x, wa.x, acc[0]);
            acc[1] = fmaf(x, wa.y, acc[1]);
            acc[2] = fmaf(x, wa.z, acc[2]);
            acc[3] = fmaf(x, wa.w, acc[3]);
            acc[4] = fmaf(x, wb.x, acc[4]);
            acc[5] = fmaf(x, wb.y, acc[5]);
            acc[6] = fmaf(x, wb.z, acc[6]);
            acc[7] = fmaf(x, wb.w, acc[7]);
        }
        float* hrow = h1s + k * H1 + jg * 8;
#pragma unroll
        for (int i = 0; i < 8; ++i) hrow[i] = fmaxf(acc[i], 0.0f);
    }
    __syncthreads();

    // ---- load W2 column into registers AFTER phase 1 (peak-pressure fix) ----
    const int d = t & 127;               // output channel for phase 2
    unsigned long long w2r[H1 / 2];      // W2 column as 32 packed f32x2
#pragma unroll
    for (int j2 = 0; j2 < H1 / 2; ++j2) {
        float wlo = W2[(2 * j2)     * H2 + d];
        float whi = W2[(2 * j2 + 1) * H2 + d];
        w2r[j2] = pack2(wlo, whi);
    }
    const float b2d = b2[d];

    // ---- MLP2 + relu + max-pool: thread t -> (d = t&127, half = t>>7) ----
    float best = 0.0f;                   // relu outputs are >= 0
    const int kbase = (t >> 7) * 16;
    for (int kk = 0; kk < 16; ++kk) {
        const int k2 = kbase + kk;
        const unsigned long long* hp =
            (const unsigned long long*)(h1s + k2 * H1);
        unsigned long long acc2 = 0ull;  // (0.0f, 0.0f)
#pragma unroll
        for (int j2 = 0; j2 < H1 / 2; ++j2)
            acc2 = fma2(hp[j2], w2r[j2], acc2);
        float lo, hiv;
        unpack2(acc2, lo, hiv);
        float s = lo + hiv + b2d;
        best = fmaxf(best, s);           // fmax with 0-init == relu-then-max
    }

    if (t >= 128) red[d] = best;
    __syncthreads();
    if (t < 128) {
        best = fmaxf(best, red[d]);
        outp[(size_t)q * H2 + d] = best;
    }
}

// ---------------------------------------------------------------------------
// launcher
// ---------------------------------------------------------------------------
extern "C" void kernel_launch(void* const* d_in, const int* in_sizes, int n_in,
                              void* d_out, int out_size)
{
    const float* pos  = (const float*)d_in[0];   // [16,4096,3]
    const float* feat = (const float*)d_in[1];   // [16,4096,64]
    const float* W1   = (const float*)d_in[2];   // [67,64]
    const float* b1   = (const float*)d_in[3];   // [64]
    const float* W2   = (const float*)d_in[4];   // [64,128]
    const float* b2   = (const float*)d_in[5];   // [128]
    const void*  idxp = d_in[6];                 // [16,1024] int64 or int32

    float* out_posq = (float*)d_out;                          // 16*1024*3
    float* out_feat = (float*)d_out + (size_t)Bdim * Mq * 3;  // 16*1024*128

    knn_kernel<<<Bdim * (Mq / QPB), KTPB>>>(pos, idxp, out_posq);

    mlp_kernel<<<Bdim * Mq, MLP_TPB>>>(pos, feat, W1, b1, W2, b2, idxp, out_feat);
}

// round 6
// speedup vs baseline: 6.2845x; 1.6291x over previous
#include <cuda_runtime.h>
#include <float.h>

#define Bdim 16
#define Npts 4096
#define Mq   1024
#define CIN  64
#define KNN  32
#define CH   (CIN + 3)   // 67 input channels (rel xyz + features)
#define H1   64
#define H2   128

// neighbor index scratch (order within each group irrelevant: downstream is
// gather + max-pool, permutation invariant)
__device__ int g_nn[Bdim * Mq * KNN];

typedef unsigned long long ull;

// ---------------------------------------------------------------------------
// helpers
// ---------------------------------------------------------------------------
__device__ __forceinline__ ull pack2(float lo, float hi) {
    ull r;
    asm("mov.b64 %0, {%1, %2};" : "=l"(r) : "f"(lo), "f"(hi));
    return r;
}
__device__ __forceinline__ void unpack2(ull v, float& lo, float& hi) {
    asm("mov.b64 {%0, %1}, %2;" : "=f"(lo), "=f"(hi) : "l"(v));
}
__device__ __forceinline__ ull fma2(ull a, ull b, ull c) {
    ull r;
    asm("fma.rn.f32x2 %0, %1, %2, %3;" : "=l"(r) : "l"(a), "l"(b), "l"(c));
    return r;
}

// idx dtype detection: int64 values < 4096 -> all odd 32-bit words are 0.
__device__ __forceinline__ int idx_is64(const void* idxp) {
    const int* p = (const int*)idxp;
    int acc = p[1] | p[3] | p[5] | p[7] | p[9] | p[11] | p[13] | p[15];
    return acc == 0;
}
__device__ __forceinline__ long long load_idx2(const void* idxp, int i, int is64) {
    return is64 ? ((const long long*)idxp)[i] : (long long)((const int*)idxp)[i];
}

// ordered-float transform: total order on float bits as unsigned
__device__ __forceinline__ unsigned ordflt(float f) {
    unsigned fb = __float_as_uint(f);
    return fb ^ ((unsigned)((int)fb >> 31) | 0x80000000u);
}

// ---------------------------------------------------------------------------
// KNN kernel v3: warp per query, 2-pass radix select with 2048-bin histogram.
//   pass 1: per-warp u16 histogram over ordered-float bits [31:21]
//   pass 2: ballot-compacted collect of definite selects + boundary list
//   remainder: warp-cooperative argmin over (key, idx) — top_k tie semantics.
// ---------------------------------------------------------------------------
#define KQPB   8      // queries (warps) per block
#define KTPB   256
#define NBIN   2048

__global__ void __launch_bounds__(KTPB)
knn_kernel(const float* __restrict__ pos,
           const void*  __restrict__ idxp,
           float* __restrict__ out_posq)
{
    __shared__ __align__(16) float4 sp[Npts];                 // 64 KB
    __shared__ __align__(16) unsigned short hist[KQPB][NBIN]; // 32 KB
    __shared__ __align__(16) ull blist[KQPB][128];            // 8 KB

    const int tid  = threadIdx.x;
    const int w    = tid >> 5;
    const int lane = tid & 31;
    const unsigned lt = (1u << lane) - 1u;
    const int b    = blockIdx.x >> 7;                 // 128 blocks per batch
    const int m    = ((blockIdx.x & 127) << 3) | w;
    const int q    = (b << 10) | m;

    const float* posb = pos + b * Npts * 3;

    // zero this warp's histogram (4 KB -> 8 uint4 stores per lane)
    {
        uint4* hz = (uint4*)hist[w];
        uint4 z = make_uint4(0, 0, 0, 0);
#pragma unroll
        for (int i = lane; i < NBIN * 2 / 16; i += 32) hz[i] = z;
    }

    // stage the full point tile once
    for (int i = tid; i < Npts; i += KTPB) {
        float px = posb[i * 3 + 0];
        float py = posb[i * 3 + 1];
        float pz = posb[i * 3 + 2];
        sp[i] = make_float4(px, py, pz, px * px + py * py + pz * pz);
    }

    const int is64 = idx_is64(idxp);
    const long long qi = load_idx2(idxp, q, is64);
    const float qx = posb[qi * 3 + 0];
    const float qy = posb[qi * 3 + 1];
    const float qz = posb[qi * 3 + 2];
    const float qn = qx * qx + qy * qy + qz * qz;

    if (lane == 0) {
        out_posq[q * 3 + 0] = qx;
        out_posq[q * 3 + 1] = qy;
        out_posq[q * 3 + 2] = qz;
    }
    __syncthreads();

    // ---------------- pass 1: histogram ----------------
    for (int i = lane; i < Npts; i += 32) {
        float4 p = sp[i];
        float d2 = fmaf(-2.0f, fmaf(qx, p.x, fmaf(qy, p.y, qz * p.z)), qn + p.w);
        unsigned bin = ordflt(d2) >> 21;
        unsigned mm = __match_any_sync(0xffffffffu, bin);
        if ((mm & lt) == 0)   // lowest lane of each equal-bin group
            hist[w][bin] = (unsigned short)(hist[w][bin] + (unsigned)__popc(mm));
    }
    __syncwarp();

    // ---------------- boundary-bin search ----------------
    int B = 0; unsigned below = 0;
    {
        const int base = lane * (NBIN / 32);
        unsigned s = 0;
#pragma unroll 8
        for (int j = 0; j < NBIN / 32; ++j) s += hist[w][base + j];
        // inclusive warp scan
        unsigned incl = s;
#pragma unroll
        for (int d_ = 1; d_ < 32; d_ <<= 1) {
            unsigned t_ = __shfl_up_sync(0xffffffffu, incl, d_);
            if (lane >= d_) incl += t_;
        }
        unsigned excl = incl - s;
        unsigned bal = __ballot_sync(0xffffffffu, incl >= (unsigned)KNN);
        int L = __ffs(bal) - 1;
        if (lane == L) {
            unsigned cum = excl;
            for (int j = 0; j < NBIN / 32; ++j) {
                unsigned c = hist[w][base + j];
                if (cum + c >= (unsigned)KNN) { B = base + j; below = cum; break; }
                cum += c;
            }
        }
        B = __shfl_sync(0xffffffffu, B, L);
        below = __shfl_sync(0xffffffffu, below, L);
    }

    // ---------------- pass 2: collect ----------------
    int outn = 0, brun = 0;
    int* dst = g_nn + q * KNN;

    for (int i = lane; i < Npts; i += 32) {
        float4 p = sp[i];
        float d2 = fmaf(-2.0f, fmaf(qx, p.x, fmaf(qy, p.y, qz * p.z)), qn + p.w);
        unsigned orf = ordflt(d2);
        int bin = (int)(orf >> 21);
        bool sel = bin < B;
        bool bnd = bin == B;

        unsigned sm = __ballot_sync(0xffffffffu, sel);
        if (sel) dst[outn + __popc(sm & lt)] = i;
        outn += __popc(sm);

        unsigned bm = __ballot_sync(0xffffffffu, bnd);
        if (bnd) {
            int s_ = brun + __popc(bm & lt);
            if (s_ < 128) blist[w][s_] = (((ull)orf) << 32) | (unsigned)i;
        }
        brun += __popc(bm);
    }
    __syncwarp();

    const int r = KNN - outn;   // outn == below

    if (brun <= 128) {
        // warp-cooperative selection of r smallest (key,idx) from the list
        ull e[4];
#pragma unroll
        for (int t_ = 0; t_ < 4; ++t_) {
            int id = t_ * 32 + lane;
            e[t_] = (id < brun) ? blist[w][id] : ~0ull;
        }
        for (int s_ = 0; s_ < r; ++s_) {
            ull lm = e[0];
            lm = e[1] < lm ? e[1] : lm;
            lm = e[2] < lm ? e[2] : lm;
            lm = e[3] < lm ? e[3] : lm;
            ull wm = lm;
#pragma unroll
            for (int d_ = 16; d_ > 0; d_ >>= 1) {
                ull o = __shfl_xor_sync(0xffffffffu, wm, d_);
                wm = o < wm ? o : wm;
            }
            if (lane == 0) dst[outn + s_] = (int)(wm & 0xffffffffu);
            // winner clears its entry (keys unique: include idx)
#pragma unroll
            for (int t_ = 0; t_ < 4; ++t_)
                if (e[t_] == wm) e[t_] = ~0ull;
        }
    } else {
        // cold fallback (pathological tie density): repeated warp-min rescans
        ull last = 0ull;
        for (int s_ = 0; s_ < r; ++s_) {
            ull best = ~0ull;
            for (int i = lane; i < Npts; i += 32) {
                float4 p = sp[i];
                float d2 = fmaf(-2.0f, fmaf(qx, p.x, fmaf(qy, p.y, qz * p.z)), qn + p.w);
                unsigned orf = ordflt(d2);
                if ((int)(orf >> 21) == B) {
                    ull key = (((ull)orf) << 32) | (unsigned)i;
                    if (key > last && key < best) best = key;
                }
            }
#pragma unroll
            for (int d_ = 16; d_ > 0; d_ >>= 1) {
                ull o = __shfl_xor_sync(0xffffffffu, best, d_);
                best = o < best ? o : best;
            }
            if (lane == 0) dst[outn + s_] = (int)(best & 0xffffffffu);
            last = best;
        }
    }
}

// ---------------------------------------------------------------------------
// MLP v2: 4 queries per block (128 rows), register-tiled GEMMs with f32x2.
//   phase 1: [128 x 67] @ [67 x 64], thread tile 4 rows x 8 cols
//   phase 2: [128 x 64] @ [64 x 128], thread tile 4 rows x 16 cols
//   h1^T aliases X^T smem; max-pool scratch aliases W1 smem.
// ---------------------------------------------------------------------------
#define MQPB    4
#define MLP_TPB 256

__global__ void __launch_bounds__(MLP_TPB, 2)
mlp_kernel(const float* __restrict__ pos,
           const float* __restrict__ feat,
           const float* __restrict__ W1,
           const float* __restrict__ b1,
           const float* __restrict__ W2,
           const float* __restrict__ b2,
           const void*  __restrict__ idxp,
           float* __restrict__ outp)
{
    __shared__ __align__(16) float W1s[CH * H1];     // 17.2 KB; later: redscr[32][129]
    __shared__ __align__(16) float W2s[H1 * H2];     // 32 KB
    __shared__ __align__(16) float xsT[CH * 128];    // 34.3 KB; later: h1T[64][128]

    const int t  = threadIdx.x;
    const int q0 = blockIdx.x * MQPB;
    const int b  = q0 >> 10;

    // ---- stage weights ----
    for (int i = t; i < CH * H1 / 4; i += MLP_TPB)
        ((float4*)W1s)[i] = ((const float4*)W1)[i];
    for (int i = t; i < H1 * H2 / 4; i += MLP_TPB)
        ((float4*)W2s)[i] = ((const float4*)W2)[i];

    // ---- gather: 2 threads per row, transposed store xsT[c][row] ----
    {
        const int row  = t >> 1;        // 0..127
        const int half = t & 1;
        const int lq   = row >> 5;
        const int k    = row & 31;
        const int q    = q0 + lq;

        const float* posb = pos + (size_t)b * Npts * 3;
        const int is64 = idx_is64(idxp);
        const long long qi = load_idx2(idxp, q, is64);
        const int n = g_nn[(size_t)q * KNN + k];

        if (half == 0) {
            xsT[0 * 128 + row] = posb[n * 3 + 0] - posb[qi * 3 + 0];
            xsT[1 * 128 + row] = posb[n * 3 + 1] - posb[qi * 3 + 1];
            xsT[2 * 128 + row] = posb[n * 3 + 2] - posb[qi * 3 + 2];
        }
        const float4* f4 = (const float4*)(feat + ((size_t)b * Npts + n) * CIN);
#pragma unroll
        for (int r_ = 0; r_ < 8; ++r_) {
            float4 v = f4[half * 8 + r_];
            int c0 = 3 + half * 32 + r_ * 4;
            xsT[(c0 + 0) * 128 + row] = v.x;
            xsT[(c0 + 1) * 128 + row] = v.y;
            xsT[(c0 + 2) * 128 + row] = v.z;
            xsT[(c0 + 3) * 128 + row] = v.w;
        }
    }
    __syncthreads();

    // ---- phase 1: tile 4 rows (tk) x 8 cols (tj), f32x2 over j-pairs ----
    const int tk = t & 31;
    const int tj = t >> 5;

    ull acc1[4][4];
    {
        float4 bA = ((const float4*)b1)[tj * 2];
        float4 bB = ((const float4*)b1)[tj * 2 + 1];
        ull bp[4] = { pack2(bA.x, bA.y), pack2(bA.z, bA.w),
                      pack2(bB.x, bB.y), pack2(bB.z, bB.w) };
#pragma unroll
        for (int r_ = 0; r_ < 4; ++r_)
#pragma unroll
            for (int p_ = 0; p_ < 4; ++p_) acc1[r_][p_] = bp[p_];
    }

    for (int c = 0; c < CH; ++c) {
        float4 xv = *(const float4*)&xsT[c * 128 + tk * 4];
        ulonglong2 wA = *(const ulonglong2*)&W1s[c * H1 + tj * 8];      // j0..3
        ulonglong2 wB = *(const ulonglong2*)&W1s[c * H1 + tj * 8 + 4];  // j4..7
        ull x0 = pack2(xv.x, xv.x);
        ull x1 = pack2(xv.y, xv.y);
        ull x2 = pack2(xv.z, xv.z);
        ull x3 = pack2(xv.w, xv.w);
        acc1[0][0] = fma2(x0, wA.x, acc1[0][0]);
        acc1[0][1] = fma2(x0, wA.y, acc1[0][1]);
        acc1[0][2] = fma2(x0, wB.x, acc1[0][2]);
        acc1[0][3] = fma2(x0, wB.y, acc1[0][3]);
        acc1[1][0] = fma2(x1, wA.x, acc1[1][0]);
        acc1[1][1] = fma2(x1, wA.y, acc1[1][1]);
        acc1[1][2] = fma2(x1, wB.x, acc1[1][2]);
        acc1[1][3] = fma2(x1, wB.y, acc1[1][3]);
        acc1[2][0] = fma2(x2, wA.x, acc1[2][0]);
        acc1[2][1] = fma2(x2, wA.y, acc1[2][1]);
        acc1[2][2] = fma2(x2, wB.x, acc1[2][2]);
        acc1[2][3] = fma2(x2, wB.y, acc1[2][3]);
        acc1[3][0] = fma2(x3, wA.x, acc1[3][0]);
        acc1[3][1] = fma2(x3, wA.y, acc1[3][1]);
        acc1[3][2] = fma2(x3, wB.x, acc1[3][2]);
        acc1[3][3] = fma2(x3, wB.y, acc1[3][3]);
    }
    __syncthreads();   // all xsT reads complete before h1T overwrite

    // ---- epilogue 1: relu + transposed store h1T[j][row] (aliases xsT) ----
    float* h1T = xsT;
#pragma unroll
    for (int p_ = 0; p_ < 4; ++p_) {
        float v0[4], v1[4];
#pragma unroll
        for (int r_ = 0; r_ < 4; ++r_) {
            float a_, b_;
            unpack2(acc1[r_][p_], a_, b_);
            v0[r_] = fmaxf(a_, 0.0f);
            v1[r_] = fmaxf(b_, 0.0f);
        }
        int j0 = tj * 8 + p_ * 2;
        *(float4*)&h1T[(j0)     * 128 + tk * 4] = make_float4(v0[0], v0[1], v0[2], v0[3]);
        *(float4*)&h1T[(j0 + 1) * 128 + tk * 4] = make_float4(v1[0], v1[1], v1[2], v1[3]);
    }
    __syncthreads();

    // ---- phase 2: tile 4 rows (tk) x 16 cols (td), f32x2 over d-pairs ----
    const int td = t >> 5;   // 8 d-tiles of 16
    ull acc2[4][8];
#pragma unroll
    for (int r_ = 0; r_ < 4; ++r_)
#pragma unroll
        for (int p_ = 0; p_ < 8; ++p_) acc2[r_][p_] = 0ull;

    for (int j = 0; j < H1; ++j) {
        float4 hv = *(const float4*)&h1T[j * 128 + tk * 4];
        const ulonglong2* wp = (const ulonglong2*)&W2s[j * H2 + td * 16];
        ulonglong2 wA = wp[0], wB = wp[1], wC = wp[2], wD = wp[3];  // d-pairs 0..7
        ull h0 = pack2(hv.x, hv.x);
        ull h1v = pack2(hv.y, hv.y);
        ull h2 = pack2(hv.z, hv.z);
        ull h3 = pack2(hv.w, hv.w);
        acc2[0][0] = fma2(h0, wA.x, acc2[0][0]);
        acc2[0][1] = fma2(h0, wA.y, acc2[0][1]);
        acc2[0][2] = fma2(h0, wB.x, acc2[0][2]);
        acc2[0][3] = fma2(h0, wB.y, acc2[0][3]);
        acc2[0][4] = fma2(h0, wC.x, acc2[0][4]);
        acc2[0][5] = fma2(h0, wC.y, acc2[0][5]);
        acc2[0][6] = fma2(h0, wD.x, acc2[0][6]);
        acc2[0][7] = fma2(h0, wD.y, acc2[0][7]);
        acc2[1][0] = fma2(h1v, wA.x, acc2[1][0]);
        acc2[1][1] = fma2(h1v, wA.y, acc2[1][1]);
        acc2[1][2] = fma2(h1v, wB.x, acc2[1][2]);
        acc2[1][3] = fma2(h1v, wB.y, acc2[1][3]);
        acc2[1][4] = fma2(h1v, wC.x, acc2[1][4]);
        acc2[1][5] = fma2(h1v, wC.y, acc2[1][5]);
        acc2[1][6] = fma2(h1v, wD.x, acc2[1][6]);
        acc2[1][7] = fma2(h1v, wD.y, acc2[1][7]);
        acc2[2][0] = fma2(h2, wA.x, acc2[2][0]);
        acc2[2][1] = fma2(h2, wA.y, acc2[2][1]);
        acc2[2][2] = fma2(h2, wB.x, acc2[2][2]);
        acc2[2][3] = fma2(h2, wB.y, acc2[2][3]);
        acc2[2][4] = fma2(h2, wC.x, acc2[2][4]);
        acc2[2][5] = fma2(h2, wC.y, acc2[2][5]);
        acc2[2][6] = fma2(h2, wD.x, acc2[2][6]);
        acc2[2][7] = fma2(h2, wD.y, acc2[2][7]);
        acc2[3][0] = fma2(h3, wA.x, acc2[3][0]);
        acc2[3][1] = fma2(h3, wA.y, acc2[3][1]);
        acc2[3][2] = fma2(h3, wB.x, acc2[3][2]);
        acc2[3][3] = fma2(h3, wB.y, acc2[3][3]);
        acc2[3][4] = fma2(h3, wC.x, acc2[3][4]);
        acc2[3][5] = fma2(h3, wC.y, acc2[3][5]);
        acc2[3][6] = fma2(h3, wD.x, acc2[3][6]);
        acc2[3][7] = fma2(h3, wD.y, acc2[3][7]);
    }
    __syncthreads();   // W1s reads long done; reuse as reduction scratch

    // ---- epilogue 2: per-thread max over 4 rows, scratch, final reduce ----
    float* redscr = W1s;   // [32][129]
#pragma unroll
    for (int p_ = 0; p_ < 8; ++p_) {
        float e0, o0, e1, o1, e2, o2, e3, o3;
        unpack2(acc2[0][p_], e0, o0);
        unpack2(acc2[1][p_], e1, o1);
        unpack2(acc2[2][p_], e2, o2);
        unpack2(acc2[3][p_], e3, o3);
        float me = fmaxf(fmaxf(e0, e1), fmaxf(e2, e3));
        float mo = fmaxf(fmaxf(o0, o1), fmaxf(o2, o3));
        redscr[tk * 129 + td * 16 + p_ * 2 + 0] = me;
        redscr[tk * 129 + td * 16 + p_ * 2 + 1] = mo;
    }
    __syncthreads();

    for (int o = t; o < MQPB * H2; o += MLP_TPB) {
        int lq = o >> 7;
        int d  = o & 127;
        float mx = -FLT_MAX;
#pragma unroll
        for (int s_ = 0; s_ < 8; ++s_)
            mx = fmaxf(mx, redscr[(lq * 8 + s_) * 129 + d]);
        outp[(size_t)(q0 + lq) * H2 + d] = fmaxf(mx + b2[d], 0.0f);
    }
}

// ---------------------------------------------------------------------------
// launcher
// ---------------------------------------------------------------------------
extern "C" void kernel_launch(void* const* d_in, const int* in_sizes, int n_in,
                              void* d_out, int out_size)
{
    const float* pos  = (const float*)d_in[0];   // [16,4096,3]
    const float* feat = (const float*)d_in[1];   // [16,4096,64]
    const float* W1   = (const float*)d_in[2];   // [67,64]
    const float* b1   = (const float*)d_in[3];   // [64]
    const float* W2   = (const float*)d_in[4];   // [64,128]
    const float* b2   = (const float*)d_in[5];   // [128]
    const void*  idxp = d_in[6];                 // [16,1024] int64 or int32

    float* out_posq = (float*)d_out;                          // 16*1024*3
    float* out_feat = (float*)d_out + (size_t)Bdim * Mq * 3;  // 16*1024*128

    knn_kernel<<<Bdim * (Mq / KQPB), KTPB>>>(pos, idxp, out_posq);

    mlp_kernel<<<(Bdim * Mq) / MQPB, MLP_TPB>>>(pos, feat, W1, b1, W2, b2,
                                                idxp, out_feat);
}

// round 8
// speedup vs baseline: 7.2726x; 1.1572x over previous
#include <cuda_runtime.h>
#include <float.h>

#define Bdim 16
#define Npts 4096
#define Mq   1024
#define CIN  64
#define KNN  32
#define CH   (CIN + 3)   // 67 input channels (rel xyz + features)
#define H1   64
#define H2   128

// scratch: neighbor indices + precomputed feature part of layer 1
__device__ int   g_nn[Bdim * Mq * KNN];
__device__ float g_h1pre[Bdim * Npts * H1];   // feat @ W1[3:] + b1 (pre-relu)

typedef unsigned long long ull;

// ---------------------------------------------------------------------------
// helpers
// ---------------------------------------------------------------------------
__device__ __forceinline__ ull pack2(float lo, float hi) {
    ull r;
    asm("mov.b64 %0, {%1, %2};" : "=l"(r) : "f"(lo), "f"(hi));
    return r;
}
__device__ __forceinline__ void unpack2(ull v, float& lo, float& hi) {
    asm("mov.b64 {%0, %1}, %2;" : "=f"(lo), "=f"(hi) : "l"(v));
}
__device__ __forceinline__ ull fma2(ull a, ull b, ull c) {
    ull r;
    asm("fma.rn.f32x2 %0, %1, %2, %3;" : "=l"(r) : "l"(a), "l"(b), "l"(c));
    return r;
}

// idx dtype detection: int64 values < 4096 -> all odd 32-bit words are 0.
__device__ __forceinline__ int idx_is64(const void* idxp) {
    const int* p = (const int*)idxp;
    int acc = p[1] | p[3] | p[5] | p[7] | p[9] | p[11] | p[13] | p[15];
    return acc == 0;
}
__device__ __forceinline__ long long load_idx2(const void* idxp, int i, int is64) {
    return is64 ? ((const long long*)idxp)[i] : (long long)((const int*)idxp)[i];
}

// ordered-float transform: total order on float bits as unsigned
__device__ __forceinline__ unsigned ordflt(float f) {
    unsigned fb = __float_as_uint(f);
    return fb ^ ((unsigned)((int)fb >> 31) | 0x80000000u);
}

// ---------------------------------------------------------------------------
// KNN kernel v4: warp per query, 2-pass radix select, 16 warps/block,
// 4x ILP unroll, atomic-based rare-path compaction (no per-iter ballots).
// ---------------------------------------------------------------------------
#define KQPB   16     // queries (warps) per block
#define KTPB   512
#define NBIN   2048

__global__ void __launch_bounds__(KTPB)
knn_kernel(const float* __restrict__ pos,
           const void*  __restrict__ idxp,
           float* __restrict__ out_posq)
{
    __shared__ __align__(16) float4 sp[Npts];                 // 64 KB
    __shared__ __align__(16) unsigned short hist[KQPB][NBIN]; // 64 KB
    __shared__ __align__(16) ull blist[KQPB][128];            // 16 KB
    __shared__ int scnt[KQPB], bcnt[KQPB];

    const int tid  = threadIdx.x;
    const int w    = tid >> 5;
    const int lane = tid & 31;
    const unsigned lt = (1u << lane) - 1u;
    const int b    = blockIdx.x >> 6;                 // 64 blocks per batch
    const int m    = ((blockIdx.x & 63) << 4) | w;
    const int q    = (b << 10) | m;

    const float* posb = pos + b * Npts * 3;

    // zero this warp's histogram (4 KB -> 8 uint4 stores per lane)
    {
        uint4* hz = (uint4*)hist[w];
        uint4 z = make_uint4(0, 0, 0, 0);
#pragma unroll
        for (int i = lane; i < NBIN * 2 / 16; i += 32) hz[i] = z;
    }
    if (lane == 0) { scnt[w] = 0; bcnt[w] = 0; }

    // stage the full point tile once
    for (int i = tid; i < Npts; i += KTPB) {
        float px = posb[i * 3 + 0];
        float py = posb[i * 3 + 1];
        float pz = posb[i * 3 + 2];
        sp[i] = make_float4(px, py, pz, px * px + py * py + pz * pz);
    }

    const int is64 = idx_is64(idxp);
    const long long qi = load_idx2(idxp, q, is64);
    const float qx = posb[qi * 3 + 0];
    const float qy = posb[qi * 3 + 1];
    const float qz = posb[qi * 3 + 2];
    const float qn = qx * qx + qy * qy + qz * qz;

    if (lane == 0) {
        out_posq[q * 3 + 0] = qx;
        out_posq[q * 3 + 1] = qy;
        out_posq[q * 3 + 2] = qz;
    }
    __syncthreads();

    // ---------------- pass 1: histogram (4x ILP) ----------------
    for (int o = 0; o < Npts; o += 128) {
        unsigned bin[4];
#pragma unroll
        for (int u = 0; u < 4; ++u) {
            float4 p = sp[o + u * 32 + lane];
            float d2 = fmaf(-2.0f, fmaf(qx, p.x, fmaf(qy, p.y, qz * p.z)), qn + p.w);
            bin[u] = ordflt(d2) >> 21;
        }
#pragma unroll
        for (int u = 0; u < 4; ++u) {
            unsigned mm = __match_any_sync(0xffffffffu, bin[u]);
            if ((mm & lt) == 0)   // lowest lane of each equal-bin group
                hist[w][bin[u]] = (unsigned short)(hist[w][bin[u]] + (unsigned)__popc(mm));
        }
    }
    __syncwarp();

    // ---------------- boundary-bin search ----------------
    int B = 0; unsigned below = 0;
    {
        const int base = lane * (NBIN / 32);
        unsigned s = 0;
#pragma unroll 8
        for (int j = 0; j < NBIN / 32; ++j) s += hist[w][base + j];
        unsigned incl = s;
#pragma unroll
        for (int d_ = 1; d_ < 32; d_ <<= 1) {
            unsigned t_ = __shfl_up_sync(0xffffffffu, incl, d_);
            if (lane >= d_) incl += t_;
        }
        unsigned excl = incl - s;
        unsigned bal = __ballot_sync(0xffffffffu, incl >= (unsigned)KNN);
        int L = __ffs(bal) - 1;
        if (lane == L) {
            unsigned cum = excl;
            for (int j = 0; j < NBIN / 32; ++j) {
                unsigned c = hist[w][base + j];
                if (cum + c >= (unsigned)KNN) { B = base + j; below = cum; break; }
                cum += c;
            }
        }
        B = __shfl_sync(0xffffffffu, B, L);
        below = __shfl_sync(0xffffffffu, below, L);
    }

    // ---------------- pass 2: collect (4x ILP, rare-path atomics) ----------
    int* dst = g_nn + q * KNN;
    const unsigned uB = (unsigned)B;

    for (int o = 0; o < Npts; o += 128) {
        unsigned orf[4];
#pragma unroll
        for (int u = 0; u < 4; ++u) {
            float4 p = sp[o + u * 32 + lane];
            float d2 = fmaf(-2.0f, fmaf(qx, p.x, fmaf(qy, p.y, qz * p.z)), qn + p.w);
            orf[u] = ordflt(d2);
        }
#pragma unroll
        for (int u = 0; u < 4; ++u) {
            unsigned bin = orf[u] >> 21;
            if (bin <= uB) {                       // rare (<~40/4096 per warp)
                int i = o + u * 32 + lane;
                if (bin < uB) {
                    int p_ = atomicAdd(&scnt[w], 1);
                    dst[p_] = i;
                } else {
                    int p_ = atomicAdd(&bcnt[w], 1);
                    if (p_ < 128)
                        blist[w][p_] = (((ull)orf[u]) << 32) | (unsigned)i;
                }
            }
        }
    }
    __syncwarp();

    const int outn = scnt[w];       // == below
    const int brun = bcnt[w];
    const int r = KNN - outn;

    if (brun <= 128) {
        // warp-cooperative selection of r smallest (key,idx) from the list
        ull e[4];
#pragma unroll
        for (int t_ = 0; t_ < 4; ++t_) {
            int id = t_ * 32 + lane;
            e[t_] = (id < brun) ? blist[w][id] : ~0ull;
        }
        for (int s_ = 0; s_ < r; ++s_) {
            ull lm = e[0];
            lm = e[1] < lm ? e[1] : lm;
            lm = e[2] < lm ? e[2] : lm;
            lm = e[3] < lm ? e[3] : lm;
            ull wm = lm;
#pragma unroll
            for (int d_ = 16; d_ > 0; d_ >>= 1) {
                ull o = __shfl_xor_sync(0xffffffffu, wm, d_);
                wm = o < wm ? o : wm;
            }
            if (lane == 0) dst[outn + s_] = (int)(wm & 0xffffffffu);
#pragma unroll
            for (int t_ = 0; t_ < 4; ++t_)
                if (e[t_] == wm) e[t_] = ~0ull;
        }
    } else {
        // cold fallback (pathological tie density): repeated warp-min rescans
        ull last = 0ull;
        for (int s_ = 0; s_ < r; ++s_) {
            ull best = ~0ull;
            for (int i = lane; i < Npts; i += 32) {
                float4 p = sp[i];
                float d2 = fmaf(-2.0f, fmaf(qx, p.x, fmaf(qy, p.y, qz * p.z)), qn + p.w);
                unsigned orf_ = ordflt(d2);
                if ((int)(orf_ >> 21) == B) {
                    ull key = (((ull)orf_) << 32) | (unsigned)i;
                    if (key > last && key < best) best = key;
                }
            }
#pragma unroll
            for (int d_ = 16; d_ > 0; d_ >>= 1) {
                ull o = __shfl_xor_sync(0xffffffffu, best, d_);
                best = o < best ? o : best;
            }
            if (lane == 0) dst[outn + s_] = (int)(best & 0xffffffffu);
            last = best;
        }
    }
}

// ---------------------------------------------------------------------------
// Precompute kernel: g_h1pre[n][j] = feat[n] @ W1[3:67] + b1   (pre-relu)
// Plain register-tiled GEMM, 128 rows/block, thread tile 4x8 with f32x2.
// ---------------------------------------------------------------------------
#define PRE_TPB 256

__global__ void __launch_bounds__(PRE_TPB)
pre_kernel(const float* __restrict__ feat,
           const float* __restrict__ W1,
           const float* __restrict__ b1)
{
    __shared__ __align__(16) float fT[CIN * 128];   // featT[c][row]  32 KB
    __shared__ __align__(16) float Wf[CIN * H1];    // W1 rows 3..66  16 KB

    const int t  = threadIdx.x;
    const int n0 = blockIdx.x * 128;

    // stage Wf: Wf[i] = W1[192 + i] (rows 3..66, linear)
    for (int i = t; i < CIN * H1 / 4; i += PRE_TPB)
        ((float4*)Wf)[i] = *(const float4*)(W1 + 192 + i * 4);

    // stage feat transposed
    {
        const int row  = t >> 1;
        const int half = t & 1;
        const float4* f4 = (const float4*)(feat + (size_t)(n0 + row) * CIN);
#pragma unroll
        for (int r_ = 0; r_ < 8; ++r_) {
            float4 v = f4[half * 8 + r_];
            int c0 = half * 32 + r_ * 4;
            fT[(c0 + 0) * 128 + row] = v.x;
            fT[(c0 + 1) * 128 + row] = v.y;
            fT[(c0 + 2) * 128 + row] = v.z;
            fT[(c0 + 3) * 128 + row] = v.w;
        }
    }
    __syncthreads();

    const int tk = t & 31;
    const int tj = t >> 5;

    ull acc[4][4];
    {
        float4 bA = ((const float4*)b1)[tj * 2];
        float4 bB = ((const float4*)b1)[tj * 2 + 1];
        ull bp[4] = { pack2(bA.x, bA.y), pack2(bA.z, bA.w),
                      pack2(bB.x, bB.y), pack2(bB.z, bB.w) };
#pragma unroll
        for (int r_ = 0; r_ < 4; ++r_)
#pragma unroll
            for (int p_ = 0; p_ < 4; ++p_) acc[r_][p_] = bp[p_];
    }

    for (int c = 0; c < CIN; ++c) {
        float4 xv = *(const float4*)&fT[c * 128 + tk * 4];
        ulonglong2 wA = *(const ulonglong2*)&Wf[c * H1 + tj * 8];
        ulonglong2 wB = *(const ulonglong2*)&Wf[c * H1 + tj * 8 + 4];
        ull x0 = pack2(xv.x, xv.x);
        ull x1 = pack2(xv.y, xv.y);
        ull x2 = pack2(xv.z, xv.z);
        ull x3 = pack2(xv.w, xv.w);
        acc[0][0] = fma2(x0, wA.x, acc[0][0]);
        acc[0][1] = fma2(x0, wA.y, acc[0][1]);
        acc[0][2] = fma2(x0, wB.x, acc[0][2]);
        acc[0][3] = fma2(x0, wB.y, acc[0][3]);
        acc[1][0] = fma2(x1, wA.x, acc[1][0]);
        acc[1][1] = fma2(x1, wA.y, acc[1][1]);
        acc[1][2] = fma2(x1, wB.x, acc[1][2]);
        acc[1][3] = fma2(x1, wB.y, acc[1][3]);
        acc[2][0] = fma2(x2, wA.x, acc[2][0]);
        acc[2][1] = fma2(x2, wA.y, acc[2][1]);
        acc[2][2] = fma2(x2, wB.x, acc[2][2]);
        acc[2][3] = fma2(x2, wB.y, acc[2][3]);
        acc[3][0] = fma2(x3, wA.x, acc[3][0]);
        acc[3][1] = fma2(x3, wA.y, acc[3][1]);
        acc[3][2] = fma2(x3, wB.x, acc[3][2]);
        acc[3][3] = fma2(x3, wB.y, acc[3][3]);
    }

#pragma unroll
    for (int r_ = 0; r_ < 4; ++r_)
#pragma unroll
        for (int p_ = 0; p_ < 4; ++p_)
            *(ull*)&g_h1pre[(size_t)(n0 + tk * 4 + r_) * H1 + tj * 8 + p_ * 2]
                = acc[r_][p_];
}

// ---------------------------------------------------------------------------
// MLP v3: gather precomputed h1_pre + xyz correction + relu, then phase-2
// register-tiled GEMM [128x64]@[64x128] with f32x2, max-pool epilogue.
// FIX vs R7: __syncthreads() after staging W1x/W2s — the gather phase READS
// W1x from smem, so staging must be barrier-ordered before it (this was the
// R7 correctness failure).
// ---------------------------------------------------------------------------
#define MQPB    4
#define MLP_TPB 256

__global__ void __launch_bounds__(MLP_TPB, 2)
mlp_kernel(const float* __restrict__ pos,
           const float* __restrict__ W1,
           const float* __restrict__ W2,
           const float* __restrict__ b2,
           const void*  __restrict__ idxp,
           float* __restrict__ outp)
{
    __shared__ __align__(16) float W2s[H1 * H2];    // 32 KB
    __shared__ __align__(16) float h1T[H1 * 128];   // 32 KB; later redscr[32][129]
    __shared__ __align__(16) float W1x[3 * H1];     // xyz rows of W1

    const int t  = threadIdx.x;
    const int q0 = blockIdx.x * MQPB;
    const int b  = q0 >> 10;

    // ---- stage weights ----
    for (int i = t; i < H1 * H2 / 4; i += MLP_TPB)
        ((float4*)W2s)[i] = ((const float4*)W2)[i];
    if (t < 48) ((float4*)W1x)[t] = ((const float4*)W1)[t];
    __syncthreads();   // gather below reads W1x from smem (R7 race fix)

    // ---- gather h1_pre rows + xyz correction + relu, transposed store ----
    {
        const int row  = t >> 1;        // 0..127
        const int half = t & 1;
        const int lq   = row >> 5;
        const int k    = row & 31;
        const int q    = q0 + lq;

        const float* posb = pos + (size_t)b * Npts * 3;
        const int is64 = idx_is64(idxp);
        const long long qi = load_idx2(idxp, q, is64);
        const int n = g_nn[(size_t)q * KNN + k];

        const float x0 = posb[n * 3 + 0] - posb[qi * 3 + 0];
        const float x1 = posb[n * 3 + 1] - posb[qi * 3 + 1];
        const float x2 = posb[n * 3 + 2] - posb[qi * 3 + 2];

        const float4* pre4 = (const float4*)(g_h1pre + (size_t)((b << 12) + n) * H1);
#pragma unroll
        for (int r_ = 0; r_ < 8; ++r_) {
            float4 v = pre4[half * 8 + r_];
            int j0 = half * 32 + r_ * 4;
            float4 wx = *(const float4*)&W1x[j0];
            float4 wy = *(const float4*)&W1x[H1 + j0];
            float4 wz = *(const float4*)&W1x[2 * H1 + j0];
            v.x = fmaxf(fmaf(x0, wx.x, fmaf(x1, wy.x, fmaf(x2, wz.x, v.x))), 0.0f);
            v.y = fmaxf(fmaf(x0, wx.y, fmaf(x1, wy.y, fmaf(x2, wz.y, v.y))), 0.0f);
            v.z = fmaxf(fmaf(x0, wx.z, fmaf(x1, wy.z, fmaf(x2, wz.z, v.z))), 0.0f);
            v.w = fmaxf(fmaf(x0, wx.w, fmaf(x1, wy.w, fmaf(x2, wz.w, v.w))), 0.0f);
            h1T[(j0 + 0) * 128 + row] = v.x;
            h1T[(j0 + 1) * 128 + row] = v.y;
            h1T[(j0 + 2) * 128 + row] = v.z;
            h1T[(j0 + 3) * 128 + row] = v.w;
        }
    }
    __syncthreads();

    // ---- phase 2: tile 4 rows (tk) x 16 cols (td), f32x2 over d-pairs ----
    const int tk = t & 31;
    const int td = t >> 5;
    ull acc2[4][8];
#pragma unroll
    for (int r_ = 0; r_ < 4; ++r_)
#pragma unroll
        for (int p_ = 0; p_ < 8; ++p_) acc2[r_][p_] = 0ull;

    for (int j = 0; j < H1; ++j) {
        float4 hv = *(const float4*)&h1T[j * 128 + tk * 4];
        const ulonglong2* wp = (const ulonglong2*)&W2s[j * H2 + td * 16];
        ulonglong2 wA = wp[0], wB = wp[1], wC = wp[2], wD = wp[3];
        ull h0 = pack2(hv.x, hv.x);
        ull h1v = pack2(hv.y, hv.y);
        ull h2 = pack2(hv.z, hv.z);
        ull h3 = pack2(hv.w, hv.w);
        acc2[0][0] = fma2(h0, wA.x, acc2[0][0]);
        acc2[0][1] = fma2(h0, wA.y, acc2[0][1]);
        acc2[0][2] = fma2(h0, wB.x, acc2[0][2]);
        acc2[0][3] = fma2(h0, wB.y, acc2[0][3]);
        acc2[0][4] = fma2(h0, wC.x, acc2[0][4]);
        acc2[0][5] = fma2(h0, wC.y, acc2[0][5]);
        acc2[0][6] = fma2(h0, wD.x, acc2[0][6]);
        acc2[0][7] = fma2(h0, wD.y, acc2[0][7]);
        acc2[1][0] = fma2(h1v, wA.x, acc2[1][0]);
        acc2[1][1] = fma2(h1v, wA.y, acc2[1][1]);
        acc2[1][2] = fma2(h1v, wB.x, acc2[1][2]);
        acc2[1][3] = fma2(h1v, wB.y, acc2[1][3]);
        acc2[1][4] = fma2(h1v, wC.x, acc2[1][4]);
        acc2[1][5] = fma2(h1v, wC.y, acc2[1][5]);
        acc2[1][6] = fma2(h1v, wD.x, acc2[1][6]);
        acc2[1][7] = fma2(h1v, wD.y, acc2[1][7]);
        acc2[2][0] = fma2(h2, wA.x, acc2[2][0]);
        acc2[2][1] = fma2(h2, wA.y, acc2[2][1]);
        acc2[2][2] = fma2(h2, wB.x, acc2[2][2]);
        acc2[2][3] = fma2(h2, wB.y, acc2[2][3]);
        acc2[2][4] = fma2(h2, wC.x, acc2[2][4]);
        acc2[2][5] = fma2(h2, wC.y, acc2[2][5]);
        acc2[2][6] = fma2(h2, wD.x, acc2[2][6]);
        acc2[2][7] = fma2(h2, wD.y, acc2[2][7]);
        acc2[3][0] = fma2(h3, wA.x, acc2[3][0]);
        acc2[3][1] = fma2(h3, wA.y, acc2[3][1]);
        acc2[3][2] = fma2(h3, wB.x, acc2[3][2]);
        acc2[3][3] = fma2(h3, wB.y, acc2[3][3]);
        acc2[3][4] = fma2(h3, wC.x, acc2[3][4]);
        acc2[3][5] = fma2(h3, wC.y, acc2[3][5]);
        acc2[3][6] = fma2(h3, wD.x, acc2[3][6]);
        acc2[3][7] = fma2(h3, wD.y, acc2[3][7]);
    }
    __syncthreads();   // h1T reads done; reuse as reduction scratch

    // ---- epilogue: per-thread max over 4 rows, scratch, final reduce ----
    float* redscr = h1T;   // [32][129]
#pragma unroll
    for (int p_ = 0; p_ < 8; ++p_) {
        float e0, o0, e1, o1, e2, o2, e3, o3;
        unpack2(acc2[0][p_], e0, o0);
        unpack2(acc2[1][p_], e1, o1);
        unpack2(acc2[2][p_], e2, o2);
        unpack2(acc2[3][p_], e3, o3);
        float me = fmaxf(fmaxf(e0, e1), fmaxf(e2, e3));
        float mo = fmaxf(fmaxf(o0, o1), fmaxf(o2, o3));
        redscr[tk * 129 + td * 16 + p_ * 2 + 0] = me;
        redscr[tk * 129 + td * 16 + p_ * 2 + 1] = mo;
    }
    __syncthreads();

    for (int o = t; o < MQPB * H2; o += MLP_TPB) {
        int lq = o >> 7;
        int d  = o & 127;
        float mx = -FLT_MAX;
#pragma unroll
        for (int s_ = 0; s_ < 8; ++s_)
            mx = fmaxf(mx, redscr[(lq * 8 + s_) * 129 + d]);
        outp[(size_t)(q0 + lq) * H2 + d] = fmaxf(mx + b2[d], 0.0f);
    }
}

// ---------------------------------------------------------------------------
// launcher
// ---------------------------------------------------------------------------
extern "C" void kernel_launch(void* const* d_in, const int* in_sizes, int n_in,
                              void* d_out, int out_size)
{
    const float* pos  = (const float*)d_in[0];   // [16,4096,3]
    const float* feat = (const float*)d_in[1];   // [16,4096,64]
    const float* W1   = (const float*)d_in[2];   // [67,64]
    const float* b1   = (const float*)d_in[3];   // [64]
    const float* W2   = (const float*)d_in[4];   // [64,128]
    const float* b2   = (const float*)d_in[5];   // [128]
    const void*  idxp = d_in[6];                 // [16,1024] int64 or int32

    float* out_posq = (float*)d_out;                          // 16*1024*3
    float* out_feat = (float*)d_out + (size_t)Bdim * Mq * 3;  // 16*1024*128

    pre_kernel<<<(Bdim * Npts) / 128, PRE_TPB>>>(feat, W1, b1);

    knn_kernel<<<Bdim * (Mq / KQPB), KTPB>>>(pos, idxp, out_posq);

    mlp_kernel<<<(Bdim * Mq) / MQPB, MLP_TPB>>>(pos, W1, W2, b2, idxp, out_feat);
}